// round 4
// baseline (speedup 1.0000x reference)
#include <cuda_runtime.h>
#include <cuda_bf16.h>

#define NBATCH 256
#define LSEQ   4096
#define KER    15
#define LOUT   (LSEQ - KER + 1)   // 4082
#define DL     64
#define DC     128
#define NIV    (KER * 4)          // 60

// ---------------- precomputed matrices (device scratch) ----------------
__device__ __align__(16) float g_Wc[NIV * DC];     // Wc[iv][c]
__device__ __align__(16) float g_U[NIV * DC];      // isq * Wc * Wk^T
__device__ __align__(16) float g_V[NIV * DC];      // (Wc * Wq^T) / LOUT
__device__ __align__(16) float g_WvWc[DC * NIV];   // Wv * Wc^T
__device__ __align__(16) float g_w[DC];            // bq + Wq*conv_b
__device__ __align__(16) float g_ob[DC];           // bv + Wv*conv_b

// ---------------- setup kernel 1: Wc ----------------
__global__ void k1_wc(const float* __restrict__ emb, const float* __restrict__ conv_w) {
    __shared__ float cw[DL * KER];
    __shared__ float embS[4 * DL];
    const int c = blockIdx.x, tid = threadIdx.x;
    for (int idx = tid; idx < DL * KER; idx += 128) cw[idx] = conv_w[c * (DL * KER) + idx];
    for (int idx = tid; idx < 4 * DL;  idx += 128) embS[idx] = emb[idx];
    __syncthreads();
    if (tid < NIV) {
        int i = tid >> 2, v = tid & 3;
        float s = 0.f;
#pragma unroll 16
        for (int d = 0; d < DL; d++) s += embS[v * DL + d] * cw[d * KER + i];
        g_Wc[tid * DC + c] = s;
    }
    __syncthreads();
    cudaTriggerProgrammaticLaunchCompletion();
}

// ---------------- setup kernel 2: U, V, WvWc, w, ob (PDL on k1) ----------------
__global__ void k2_uv(const float* __restrict__ Wq, const float* __restrict__ bq,
                      const float* __restrict__ Wk, const float* __restrict__ Wv,
                      const float* __restrict__ bv, const float* __restrict__ conv_b) {
    __shared__ float wkS[DC], wqS[DC], wvS[DC], cbS[DC];
    const int c = blockIdx.x, tid = threadIdx.x;
    // prologue: independent of k1's output
    for (int idx = tid; idx < DC; idx += 64) {
        wkS[idx] = Wk[c * DC + idx];
        wqS[idx] = Wq[c * DC + idx];
        wvS[idx] = Wv[c * DC + idx];
        cbS[idx] = conv_b[idx];
    }
    __syncthreads();
    cudaGridDependencySynchronize();   // wait for g_Wc
    const float isq = 0.088388347648318447f;  // 1/sqrt(128)
    if (tid < NIV) {
        const float4* wc4 = (const float4*)(g_Wc + tid * DC);
        float su = 0.f, sv = 0.f, sw = 0.f;
#pragma unroll 8
        for (int q = 0; q < DC / 4; q++) {
            float4 f = wc4[q];
            int d = q * 4;
            su += f.x * wkS[d] + f.y * wkS[d + 1] + f.z * wkS[d + 2] + f.w * wkS[d + 3];
            sv += f.x * wqS[d] + f.y * wqS[d + 1] + f.z * wqS[d + 2] + f.w * wqS[d + 3];
            sw += f.x * wvS[d] + f.y * wvS[d + 1] + f.z * wvS[d + 2] + f.w * wvS[d + 3];
        }
        g_U[tid * DC + c] = su * isq;
        g_V[tid * DC + c] = sv * (1.0f / (float)LOUT);
        g_WvWc[c * NIV + tid] = sw;
    } else if (tid == 60) {
        float s = bq[c];
#pragma unroll 8
        for (int e = 0; e < DC; e++) s += wqS[e] * cbS[e];
        g_w[c] = s;
    } else if (tid == 61) {
        float s = bv[c];
#pragma unroll 8
        for (int e = 0; e < DC; e++) s += wvS[e] * cbS[e];
        g_ob[c] = s;
    }
    __syncthreads();
    cudaTriggerProgrammaticLaunchCompletion();
}

// ---------------- main kernel: one block per batch element (PDL on k2) ----------------
__global__ void __launch_bounds__(512, 2)
seq_main(const int* __restrict__ tokens, float* __restrict__ out) {
    __shared__ unsigned long long buckets[3072];     // 24 KB
    __shared__ float Tbl[3072];                      // 12 KB
    __shared__ unsigned int Xs[129], Ys[129];
    __shared__ float t_s[DC];
    __shared__ float S_s[NIV], fcnt_s[NIV], A_s[NIV];
    __shared__ float red_s[16];
    __shared__ float wacc[16][16];
    __shared__ float fin[46];   // [0]=E, [1+i]=Ex_i, [16+i]=Ey_i, [31+i]=Exy_i
    __shared__ int hist_s[4];

    const int tid = threadIdx.x, lane = tid & 31, warp = tid >> 5;

    // ======== prologue: independent of setup kernels ========
    for (int idx = tid; idx < 3072; idx += 512) buckets[idx] = 0ull;
    if (tid < 4) hist_s[tid] = 0;
    if (tid == 0) { Xs[128] = 0u; Ys[128] = 0u; }
    __syncthreads();

    // tokens -> bitplanes + histogram
    const int* trow = tokens + (size_t)blockIdx.x * LSEQ;
    int tv[8];
#pragma unroll
    for (int m = 0; m < 8; m++) tv[m] = trow[m * 512 + warp * 32 + lane];
    int n0 = 0, n1 = 0, n2 = 0, n3 = 0;
#pragma unroll
    for (int m = 0; m < 8; m++) {
        unsigned b0 = __ballot_sync(0xffffffffu, tv[m] & 1);
        unsigned b1 = __ballot_sync(0xffffffffu, tv[m] & 2);
        if (lane == 0) {
            int w = m * 16 + warp;
            Xs[w] = b0; Ys[w] = b1;
            int c3 = __popc(b0 & b1);
            int c1 = __popc(b0) - c3;
            int c2 = __popc(b1) - c3;
            n3 += c3; n1 += c1; n2 += c2; n0 += 32 - c1 - c2 - c3;
        }
    }
    if (lane == 0) {
        atomicAdd(&hist_s[0], n0); atomicAdd(&hist_s[1], n1);
        atomicAdd(&hist_s[2], n2); atomicAdd(&hist_s[3], n3);
    }
    __syncthreads();

#define TOK_AT(p) ((int)(((Xs[(p) >> 5] >> ((p) & 31)) & 1u) | (((Ys[(p) >> 5] >> ((p) & 31)) & 1u) << 1)))

    // sliding-window counts
    if (tid < NIV) {
        int i = tid >> 2, v = tid & 3;
        int cnt = hist_s[v];
        for (int p = 0; p < i; p++) cnt -= (TOK_AT(p) == v);
        for (int p = i + LOUT; p < LSEQ; p++) cnt -= (TOK_AT(p) == v);
        fcnt_s[tid] = (float)cnt;
    }
    __syncthreads();

    // ======== wait for setup results ========
    cudaGridDependencySynchronize();

    // t[e] = w[e] + sum_j V'[j][e] * fcnt[j]
    if (tid < DC) {
        float s = g_w[tid];
#pragma unroll 12
        for (int j = 0; j < NIV; j++) s += g_V[j * DC + tid] * fcnt_s[j];
        t_s[tid] = s;
    }
    __syncthreads();

    // S[i] = sum_e U'[i][e] * t[e]
    if (tid < NIV) {
        const float4* u4 = (const float4*)(g_U + tid * DC);
        float s = 0.f;
#pragma unroll 8
        for (int q = 0; q < DC / 4; q++) {
            float4 f = u4[q];
            int e = q * 4;
            s += f.x * t_s[e] + f.y * t_s[e + 1] + f.z * t_s[e + 2] + f.w * t_s[e + 3];
        }
        S_s[tid] = s;
    }
    __syncthreads();

    // chunk tables: Tbl[k*1024+u] = sum_{j<5} S[5k+j, v_j(u)]
    for (int idx = tid; idx < 3072; idx += 512) {
        int k = idx >> 10, u = idx & 1023;
        int xb = u & 31, yb = u >> 5;
        float s = 0.f;
#pragma unroll
        for (int j = 0; j < 5; j++) {
            int v = ((xb >> j) & 1) | (((yb >> j) & 1) << 1);
            s += S_s[(5 * k + j) * 4 + v];
        }
        Tbl[idx] = s;
    }
    __syncthreads();

    // ---- pass 1: block max, 8 consecutive positions per thread ----
    const int base = tid * 8;
    const int nj = (base < LOUT) ? ((LOUT - base < 8) ? (LOUT - base) : 8) : 0;
    const int wi = base >> 5;
    unsigned x0 = Xs[wi], x1 = Xs[wi + 1];
    unsigned y0 = Ys[wi], y1 = Ys[wi + 1];
    const int sh0 = base & 31;

    float lmax = -1e30f;
    for (int j = 0; j < nj; j++) {
        int sh = sh0 + j;
        unsigned bx = __funnelshift_r(x0, x1, sh);
        unsigned by = __funnelshift_r(y0, y1, sh);
        int u0 = (bx & 31) | ((by & 31) << 5);
        int u1 = ((bx >> 5) & 31) | (((by >> 5) & 31) << 5);
        int u2 = ((bx >> 10) & 31) | (((by >> 10) & 31) << 5);
        lmax = fmaxf(lmax, Tbl[u0] + Tbl[1024 + u1] + Tbl[2048 + u2]);
    }
#pragma unroll
    for (int o = 16; o > 0; o >>= 1)
        lmax = fmaxf(lmax, __shfl_xor_sync(0xffffffffu, lmax, o));
    if (lane == 0) red_s[warp] = lmax;
    __syncthreads();
    float bmax = red_s[0];
#pragma unroll
    for (int w = 1; w < 16; w++) bmax = fmaxf(bmax, red_s[w]);

    // ---- pass 2: exp + deterministic fixed-point scatter ----
    const float SCALE = 1099511627776.0f;  // 2^40
    for (int j = 0; j < nj; j++) {
        int sh = sh0 + j;
        unsigned bx = __funnelshift_r(x0, x1, sh);
        unsigned by = __funnelshift_r(y0, y1, sh);
        int u0 = (bx & 31) | ((by & 31) << 5);
        int u1 = ((bx >> 5) & 31) | (((by >> 5) & 31) << 5);
        int u2 = ((bx >> 10) & 31) | (((by >> 10) & 31) << 5);
        float e = __expf(Tbl[u0] + Tbl[1024 + u1] + Tbl[2048 + u2] - bmax);
        unsigned long long es = (unsigned long long)(e * SCALE);
        atomicAdd(&buckets[u0], es);
        atomicAdd(&buckets[1024 + u1], es);
        atomicAdd(&buckets[2048 + u2], es);
    }
    __syncthreads();

    // ---- post-process buckets chunk-by-chunk ----
    const float INV40 = 1.0f / 1099511627776.0f;
    for (int k = 0; k < 3; k++) {
        float acc[15];
#pragma unroll
        for (int j = 0; j < 15; j++) acc[j] = 0.f;
        float accE = 0.f;
        for (int m = tid; m < 1024; m += 512) {
            float val = (float)buckets[k * 1024 + m] * INV40;
            accE += val;
#pragma unroll
            for (int j = 0; j < 5; j++) {
                acc[j]      += ((m >> j) & 1)       ? val : 0.f;
                acc[5 + j]  += ((m >> (5 + j)) & 1) ? val : 0.f;
                acc[10 + j] += (((m >> j) & (m >> (5 + j))) & 1) ? val : 0.f;
            }
        }
#pragma unroll
        for (int j = 0; j < 15; j++) {
            float v = acc[j];
#pragma unroll
            for (int o = 16; o > 0; o >>= 1) v += __shfl_xor_sync(0xffffffffu, v, o);
            if (lane == 0) wacc[warp][j] = v;
        }
        if (k == 0) {
#pragma unroll
            for (int o = 16; o > 0; o >>= 1) accE += __shfl_xor_sync(0xffffffffu, accE, o);
            if (lane == 0) wacc[warp][15] = accE;
        }
        __syncthreads();
        if (tid < 16 && (tid < 15 || k == 0)) {
            float s = 0.f;
#pragma unroll
            for (int w = 0; w < 16; w++) s += wacc[w][tid];
            if (tid == 15) fin[0] = s;
            else {
                int jj = tid % 5, i = 5 * k + jj;
                int dest = (tid < 5) ? (1 + i) : (tid < 10) ? (16 + i) : (31 + i);
                fin[dest] = s;
            }
        }
        __syncthreads();
    }

    // ---- A[i][v] ----
    if (tid < NIV) {
        int i = tid >> 2, v = tid & 3;
        float E = fin[0], Ex = fin[1 + i], Ey = fin[16 + i], Exy = fin[31 + i];
        A_s[tid] = (v == 3) ? Exy
                 : (v == 1) ? (Ex - Exy)
                 : (v == 2) ? (Ey - Exy)
                 : (E - Ex - Ey + Exy);
    }
    __syncthreads();

    // ---- out[c] = ob[c] + (WvWc*A)[c]/E ----
    if (tid < DC) {
        const float4* w4 = (const float4*)(g_WvWc + tid * NIV);
        float s = 0.f;
#pragma unroll
        for (int q = 0; q < NIV / 4; q++) {
            float4 f = w4[q];
            int j = q * 4;
            s += f.x * A_s[j] + f.y * A_s[j + 1] + f.z * A_s[j + 2] + f.w * A_s[j + 3];
        }
        out[(size_t)blockIdx.x * DC + tid] = g_ob[tid] + s / fin[0];
    }
}

// ---------------- launch ----------------
// Inputs: tokens, emb, conv_w, conv_b, Wq, bq, Wk, bk, Wv, bv  (bk drops out of softmax)
extern "C" void kernel_launch(void* const* d_in, const int* in_sizes, int n_in,
                              void* d_out, int out_size) {
    const int*   tokens = (const int*)  d_in[0];
    const float* emb    = (const float*)d_in[1];
    const float* conv_w = (const float*)d_in[2];
    const float* conv_b = (const float*)d_in[3];
    const float* Wq     = (const float*)d_in[4];
    const float* bq     = (const float*)d_in[5];
    const float* Wk     = (const float*)d_in[6];
    const float* Wv     = (const float*)d_in[8];
    const float* bv     = (const float*)d_in[9];
    float*       out    = (float*)d_out;

    k1_wc<<<DC, 128>>>(emb, conv_w);

    cudaLaunchAttribute attr[1];
    attr[0].id = cudaLaunchAttributeProgrammaticStreamSerialization;
    attr[0].val.programmaticStreamSerializationAllowed = 1;

    {
        cudaLaunchConfig_t cfg = {};
        cfg.gridDim  = dim3(DC, 1, 1);
        cfg.blockDim = dim3(64, 1, 1);
        cfg.dynamicSmemBytes = 0;
        cfg.stream = 0;
        cfg.attrs = attr;
        cfg.numAttrs = 1;
        cudaLaunchKernelEx(&cfg, k2_uv, Wq, bq, Wk, Wv, bv, conv_b);
    }
    {
        cudaLaunchConfig_t cfg = {};
        cfg.gridDim  = dim3(NBATCH, 1, 1);
        cfg.blockDim = dim3(512, 1, 1);
        cfg.dynamicSmemBytes = 0;
        cfg.stream = 0;
        cfg.attrs = attr;
        cfg.numAttrs = 1;
        cudaLaunchKernelEx(&cfg, seq_main, tokens, out);
    }
}

// round 5
// speedup vs baseline: 1.5695x; 1.5695x over previous
#include <cuda_runtime.h>
#include <cuda_bf16.h>

#define NBATCH 256
#define LSEQ   4096
#define KER    15
#define LOUT   (LSEQ - KER + 1)   // 4082
#define DL     64
#define DC     128
#define NIV    (KER * 4)          // 60
#define NTHR   512

// ---------------- device scratch (persist across replays; rewritten each launch) ----
__device__ __align__(16) float g_Wc[NIV * DC];     // Wc[iv][c]
__device__ __align__(16) float g_U[NIV * DC];      // isq * Wc * Wk^T
__device__ __align__(16) float g_V[NIV * DC];      // (Wc * Wq^T) / LOUT
__device__ __align__(16) float g_WvWc[DC * NIV];   // Wv * Wc^T
__device__ __align__(16) float g_w[DC];            // bq + Wq*conv_b
__device__ __align__(16) float g_ob[DC];           // bv + Wv*conv_b

// ---------------- software grid barrier (sense-reversing; state persists OK) -------
__device__ unsigned g_barc = 0;
__device__ volatile unsigned g_sense = 0;

__device__ __forceinline__ void grid_barrier(int tid) {
    __syncthreads();
    if (tid == 0) {
        unsigned s = g_sense;
        __threadfence();                       // release: publish our global writes
        unsigned old = atomicAdd(&g_barc, 1u);
        if (old == NBATCH - 1) {
            g_barc = 0;
            __threadfence();
            g_sense = s ^ 1u;                  // release everyone
        } else {
            while (g_sense == s) { }           // spin (volatile load)
        }
        __threadfence();                       // acquire
    }
    __syncthreads();
}

// ---------------- the whole problem in ONE kernel -----------------------------------
// 256 blocks x 512 threads, <=64 regs, ~16KB smem  =>  2 blocks/SM => 296 slots >= 256
// so all blocks are co-resident and the spin barrier is safe.
__global__ void __launch_bounds__(NTHR, 2)
seq_all(const int*   __restrict__ tokens,
        const float* __restrict__ emb,   const float* __restrict__ conv_w,
        const float* __restrict__ conv_b,
        const float* __restrict__ Wq,    const float* __restrict__ bq,
        const float* __restrict__ Wk,    const float* __restrict__ Wv,
        const float* __restrict__ bv,    float* __restrict__ out) {
    __shared__ float Tbl[3072];                 // chunk tables; aliased as setup scratch
    __shared__ unsigned int Xs[129], Ys[129];   // token bitplanes
    __shared__ float t_s[DC];
    __shared__ float S_s[NIV], fcnt_s[NIV], A_s[NIV];
    __shared__ float red_s[16];
    __shared__ float wacc[16][16];
    __shared__ float fin[46];                   // [0]=E, [1+i]=Ex, [16+i]=Ey, [31+i]=Exy
    __shared__ int hist_s[4];

    const int tid = threadIdx.x, lane = tid & 31, warp = tid >> 5;
    const int bid = blockIdx.x;
    float* scratch = Tbl;                       // setup scratch aliases Tbl

    if (tid < 4) hist_s[tid] = 0;
    if (tid == 0) { Xs[128] = 0u; Ys[128] = 0u; }
    __syncthreads();

    // ======== prologue (all blocks): tokens -> bitplanes + histogram ========
    const int* trow = tokens + (size_t)bid * LSEQ;
    int tv[8];
#pragma unroll
    for (int m = 0; m < 8; m++) tv[m] = trow[m * NTHR + warp * 32 + lane];
    int n0 = 0, n1 = 0, n2 = 0, n3 = 0;
#pragma unroll
    for (int m = 0; m < 8; m++) {
        unsigned b0 = __ballot_sync(0xffffffffu, tv[m] & 1);
        unsigned b1 = __ballot_sync(0xffffffffu, tv[m] & 2);
        if (lane == 0) {
            Xs[m * 16 + warp] = b0; Ys[m * 16 + warp] = b1;
            int c3 = __popc(b0 & b1);
            int c1 = __popc(b0) - c3;
            int c2 = __popc(b1) - c3;
            n3 += c3; n1 += c1; n2 += c2; n0 += 32 - c1 - c2 - c3;
        }
    }
    if (lane == 0) {
        atomicAdd(&hist_s[0], n0); atomicAdd(&hist_s[1], n1);
        atomicAdd(&hist_s[2], n2); atomicAdd(&hist_s[3], n3);
    }
    __syncthreads();

#define TOK_AT(p) ((int)(((Xs[(p) >> 5] >> ((p) & 31)) & 1u) | (((Ys[(p) >> 5] >> ((p) & 31)) & 1u) << 1)))

    if (tid < NIV) {   // sliding-window counts
        int i = tid >> 2, v = tid & 3;
        int cnt = hist_s[v];
        for (int p = 0; p < i; p++) cnt -= (TOK_AT(p) == v);
        for (int p = i + LOUT; p < LSEQ; p++) cnt -= (TOK_AT(p) == v);
        fcnt_s[tid] = (float)cnt;
    }

    // ======== setup phase 1 (blocks 0..127): Wc column c=bid ========
    if (bid < DC) {
        float* cw   = scratch;          // 960 floats: conv_w[c][d][i]
        float* embS = scratch + 960;    // 256 floats
        for (int idx = tid; idx < DL * KER; idx += NTHR) cw[idx] = conv_w[bid * (DL * KER) + idx];
        for (int idx = tid; idx < 4 * DL;  idx += NTHR) embS[idx] = emb[idx];
        __syncthreads();
        if (tid < NIV) {
            int i = tid >> 2, v = tid & 3;
            float s = 0.f;
#pragma unroll 16
            for (int d = 0; d < DL; d++) s += embS[v * DL + d] * cw[d * KER + i];
            g_Wc[tid * DC + bid] = s;
        }
    }

    grid_barrier(tid);   // g_Wc complete

    // ======== setup phase 2 (blocks 0..127): U, V, WvWc, w, ob ========
    if (bid < DC) {
        float* wkS = scratch;       float* wqS = scratch + DC;
        float* wvS = scratch + 2 * DC; float* cbS = scratch + 3 * DC;
        for (int idx = tid; idx < DC; idx += NTHR) {
            wkS[idx] = Wk[bid * DC + idx];
            wqS[idx] = Wq[bid * DC + idx];
            wvS[idx] = Wv[bid * DC + idx];
            cbS[idx] = conv_b[idx];
        }
        __syncthreads();
        const float isq = 0.088388347648318447f;  // 1/sqrt(128)
        if (tid < NIV) {
            const float4* wc4 = (const float4*)(g_Wc + tid * DC);
            float su = 0.f, sv = 0.f, sw = 0.f;
#pragma unroll 8
            for (int q = 0; q < DC / 4; q++) {
                float4 f = wc4[q];
                int d = q * 4;
                su += f.x * wkS[d] + f.y * wkS[d + 1] + f.z * wkS[d + 2] + f.w * wkS[d + 3];
                sv += f.x * wqS[d] + f.y * wqS[d + 1] + f.z * wqS[d + 2] + f.w * wqS[d + 3];
                sw += f.x * wvS[d] + f.y * wvS[d + 1] + f.z * wvS[d + 2] + f.w * wvS[d + 3];
            }
            g_U[tid * DC + bid] = su * isq;
            g_V[tid * DC + bid] = sv * (1.0f / (float)LOUT);
            g_WvWc[bid * NIV + tid] = sw;
        } else if (tid == 60) {
            float s = bq[bid];
#pragma unroll 8
            for (int e = 0; e < DC; e++) s += wqS[e] * cbS[e];
            g_w[bid] = s;
        } else if (tid == 61) {
            float s = bv[bid];
#pragma unroll 8
            for (int e = 0; e < DC; e++) s += wvS[e] * cbS[e];
            g_ob[bid] = s;
        }
    }

    grid_barrier(tid);   // g_U/g_V/g_WvWc/g_w/g_ob complete

    // ======== per-batch score table: t = w + V'^T fcnt ; S = U' t ========
    if (tid < DC) {
        float s = g_w[tid];
#pragma unroll 12
        for (int j = 0; j < NIV; j++) s += g_V[j * DC + tid] * fcnt_s[j];
        t_s[tid] = s;
    }
    __syncthreads();
    if (tid < NIV) {
        const float4* u4 = (const float4*)(g_U + tid * DC);
        float s = 0.f;
#pragma unroll 8
        for (int q = 0; q < DC / 4; q++) {
            float4 f = u4[q];
            int e = q * 4;
            s += f.x * t_s[e] + f.y * t_s[e + 1] + f.z * t_s[e + 2] + f.w * t_s[e + 3];
        }
        S_s[tid] = s;
    }
    __syncthreads();

    // ======== chunk tables: Tbl[k*1024+u] = sum_{j<5} S[5k+j, v_j(u)] ========
    for (int idx = tid; idx < 3072; idx += NTHR) {
        int k = idx >> 10, u = idx & 1023;
        int xb = u & 31, yb = u >> 5;
        float s = 0.f;
#pragma unroll
        for (int j = 0; j < 5; j++) {
            int v = ((xb >> j) & 1) | (((yb >> j) & 1) << 1);
            s += S_s[(5 * k + j) * 4 + v];
        }
        Tbl[idx] = s;
    }
    __syncthreads();

    // ======== 8 consecutive positions per thread; bitplane words cached ========
    const int base = tid * 8;
    const int nj = (base < LOUT) ? ((LOUT - base < 8) ? (LOUT - base) : 8) : 0;
    const int wi = base >> 5;
    const unsigned x0 = Xs[wi], x1 = Xs[wi + 1];
    const unsigned y0 = Ys[wi], y1 = Ys[wi + 1];
    const int sh0 = base & 31;

    // ---- pass 1: block max ----
    float lmax = -1e30f;
    for (int j = 0; j < nj; j++) {
        int sh = sh0 + j;
        unsigned bx = __funnelshift_r(x0, x1, sh);
        unsigned by = __funnelshift_r(y0, y1, sh);
        int u0 = (bx & 31) | ((by & 31) << 5);
        int u1 = ((bx >> 5) & 31) | (((by >> 5) & 31) << 5);
        int u2 = ((bx >> 10) & 31) | (((by >> 10) & 31) << 5);
        lmax = fmaxf(lmax, Tbl[u0] + Tbl[1024 + u1] + Tbl[2048 + u2]);
    }
#pragma unroll
    for (int o = 16; o > 0; o >>= 1)
        lmax = fmaxf(lmax, __shfl_xor_sync(0xffffffffu, lmax, o));
    if (lane == 0) red_s[warp] = lmax;
    __syncthreads();
    float bmax = red_s[0];
#pragma unroll
    for (int w = 1; w < 16; w++) bmax = fmaxf(bmax, red_s[w]);

    // ---- passes 2-4: register accumulation per 5-tap chunk (no atomics) ----
    for (int k = 0; k < 3; k++) {
        float acc[15];
#pragma unroll
        for (int j = 0; j < 15; j++) acc[j] = 0.f;
        float accE = 0.f;
        for (int j = 0; j < nj; j++) {
            int sh = sh0 + j;
            unsigned bx = __funnelshift_r(x0, x1, sh);
            unsigned by = __funnelshift_r(y0, y1, sh);
            int u0 = (bx & 31) | ((by & 31) << 5);
            int u1 = ((bx >> 5) & 31) | (((by >> 5) & 31) << 5);
            int u2 = ((bx >> 10) & 31) | (((by >> 10) & 31) << 5);
            float e = __expf(Tbl[u0] + Tbl[1024 + u1] + Tbl[2048 + u2] - bmax);
            accE += e;
            unsigned xb = bx >> (5 * k), yb = by >> (5 * k);
#pragma unroll
            for (int jj = 0; jj < 5; jj++) {
                unsigned X = (xb >> jj) & 1u, Y = (yb >> jj) & 1u;
                acc[jj]      += X ? e : 0.f;
                acc[5 + jj]  += Y ? e : 0.f;
                acc[10 + jj] += (X & Y) ? e : 0.f;
            }
        }
#pragma unroll
        for (int j = 0; j < 15; j++) {
            float v = acc[j];
#pragma unroll
            for (int o = 16; o > 0; o >>= 1) v += __shfl_xor_sync(0xffffffffu, v, o);
            if (lane == 0) wacc[warp][j] = v;
        }
        if (k == 0) {
#pragma unroll
            for (int o = 16; o > 0; o >>= 1) accE += __shfl_xor_sync(0xffffffffu, accE, o);
            if (lane == 0) wacc[warp][15] = accE;
        }
        __syncthreads();
        if (tid < 16 && (tid < 15 || k == 0)) {
            float s = 0.f;
#pragma unroll
            for (int w = 0; w < 16; w++) s += wacc[w][tid];
            if (tid == 15) fin[0] = s;
            else {
                int jj = tid % 5, i = 5 * k + jj;
                int dest = (tid < 5) ? (1 + i) : (tid < 10) ? (16 + i) : (31 + i);
                fin[dest] = s;
            }
        }
        __syncthreads();
    }

    // ---- A[i][v] from (E, Ex, Ey, Exy) ----
    if (tid < NIV) {
        int i = tid >> 2, v = tid & 3;
        float E = fin[0], Ex = fin[1 + i], Ey = fin[16 + i], Exy = fin[31 + i];
        A_s[tid] = (v == 3) ? Exy
                 : (v == 1) ? (Ex - Exy)
                 : (v == 2) ? (Ey - Exy)
                 : (E - Ex - Ey + Exy);
    }
    __syncthreads();

    // ---- out[c] = ob[c] + (WvWc*A)[c]/E ----
    if (tid < DC) {
        const float4* w4 = (const float4*)(g_WvWc + tid * NIV);
        float s = 0.f;
#pragma unroll
        for (int q = 0; q < NIV / 4; q++) {
            float4 f = w4[q];
            int j = q * 4;
            s += f.x * A_s[j] + f.y * A_s[j + 1] + f.z * A_s[j + 2] + f.w * A_s[j + 3];
        }
        out[(size_t)bid * DC + tid] = g_ob[tid] + s / fin[0];
    }
}

// ---------------- launch: ONE kernel ----------------
// Inputs: tokens, emb, conv_w, conv_b, Wq, bq, Wk, bk, Wv, bv  (bk drops out of softmax)
extern "C" void kernel_launch(void* const* d_in, const int* in_sizes, int n_in,
                              void* d_out, int out_size) {
    const int*   tokens = (const int*)  d_in[0];
    const float* emb    = (const float*)d_in[1];
    const float* conv_w = (const float*)d_in[2];
    const float* conv_b = (const float*)d_in[3];
    const float* Wq     = (const float*)d_in[4];
    const float* bq     = (const float*)d_in[5];
    const float* Wk     = (const float*)d_in[6];
    const float* Wv     = (const float*)d_in[8];
    const float* bv     = (const float*)d_in[9];
    float*       out    = (float*)d_out;

    seq_all<<<NBATCH, NTHR>>>(tokens, emb, conv_w, conv_b, Wq, bq, Wk, Wv, bv, out);
}

// round 6
// speedup vs baseline: 1.7600x; 1.1214x over previous
#include <cuda_runtime.h>
#include <cuda_bf16.h>

#define NBATCH 256
#define LSEQ   4096
#define KER    15
#define LOUT   (LSEQ - KER + 1)   // 4082
#define DL     64
#define DC     128
#define NIV    (KER * 4)          // 60
#define NTHR   512

// ---------------- device scratch (rewritten every launch) ----------------
__device__ __align__(16) float g_Wc[NIV * DC];     // Wc[iv][c]
__device__ __align__(16) float g_U[NIV * DC];      // isq * Wc * Wk^T
__device__ __align__(16) float g_V[NIV * DC];      // (Wc * Wq^T) / LOUT
__device__ __align__(16) float g_WvWc[DC * NIV];   // Wv * Wc^T
__device__ __align__(16) float g_w[DC];            // bq + Wq*conv_b
__device__ __align__(16) float g_ob[DC];           // bv + Wv*conv_b

// ---------------- software grid barrier (sense-reversing) ----------------
__device__ unsigned g_barc = 0;
__device__ volatile unsigned g_sense = 0;

__device__ __forceinline__ void grid_barrier(int tid) {
    __syncthreads();
    if (tid == 0) {
        unsigned s = g_sense;
        __threadfence();
        unsigned old = atomicAdd(&g_barc, 1u);
        if (old == NBATCH - 1) {
            g_barc = 0;
            __threadfence();
            g_sense = s ^ 1u;
        } else {
            while (g_sense == s) { }
        }
        __threadfence();
    }
    __syncthreads();
}

// 256 blocks x 512 threads, <=64 regs, ~16KB smem => 2 blocks/SM => all co-resident.
__global__ void __launch_bounds__(NTHR, 2)
seq_all(const int*   __restrict__ tokens,
        const float* __restrict__ emb,   const float* __restrict__ conv_w,
        const float* __restrict__ conv_b,
        const float* __restrict__ Wq,    const float* __restrict__ bq,
        const float* __restrict__ Wk,    const float* __restrict__ Wv,
        const float* __restrict__ bv,    float* __restrict__ out) {
    __shared__ float Tbl[3072];                 // chunk tables; aliased setup scratch
    __shared__ unsigned int Xs[129], Ys[129];
    __shared__ float t_s[DC];
    __shared__ float S_s[NIV], fcnt_s[NIV], A_s[NIV];
    __shared__ float red_s[16];
    __shared__ float wacc[16][16];
    __shared__ float fin[46];                   // [0]=E, [1+i]=Ex, [16+i]=Ey, [31+i]=Exy
    __shared__ int hist_s[4];
    __shared__ float bmax_s;

    const int tid = threadIdx.x, lane = tid & 31, warp = tid >> 5;
    const int bid = blockIdx.x;
    float* scratch = Tbl;

    if (tid < 4) hist_s[tid] = 0;
    if (tid == 0) { Xs[128] = 0u; Ys[128] = 0u; }
    __syncthreads();

    // ======== prologue: tokens -> bitplanes + histogram ========
    const int* trow = tokens + (size_t)bid * LSEQ;
    int tv[8];
#pragma unroll
    for (int m = 0; m < 8; m++) tv[m] = trow[m * NTHR + warp * 32 + lane];
    int n0 = 0, n1 = 0, n2 = 0, n3 = 0;
#pragma unroll
    for (int m = 0; m < 8; m++) {
        unsigned b0 = __ballot_sync(0xffffffffu, tv[m] & 1);
        unsigned b1 = __ballot_sync(0xffffffffu, tv[m] & 2);
        if (lane == 0) {
            Xs[m * 16 + warp] = b0; Ys[m * 16 + warp] = b1;
            int c3 = __popc(b0 & b1);
            int c1 = __popc(b0) - c3;
            int c2 = __popc(b1) - c3;
            n3 += c3; n1 += c1; n2 += c2; n0 += 32 - c1 - c2 - c3;
        }
    }
    if (lane == 0) {
        atomicAdd(&hist_s[0], n0); atomicAdd(&hist_s[1], n1);
        atomicAdd(&hist_s[2], n2); atomicAdd(&hist_s[3], n3);
    }
    __syncthreads();

#define TOK_AT(p) ((int)(((Xs[(p) >> 5] >> ((p) & 31)) & 1u) | (((Ys[(p) >> 5] >> ((p) & 31)) & 1u) << 1)))

    if (tid < NIV) {   // sliding-window counts
        int i = tid >> 2, v = tid & 3;
        int cnt = hist_s[v];
        for (int p = 0; p < i; p++) cnt -= (TOK_AT(p) == v);
        for (int p = i + LOUT; p < LSEQ; p++) cnt -= (TOK_AT(p) == v);
        fcnt_s[tid] = (float)cnt;
    }

    // ======== setup phase 1 (blocks 0..127): Wc column c=bid ========
    if (bid < DC) {
        float* cw   = scratch;          // 960
        float* embS = scratch + 960;    // 256
        for (int idx = tid; idx < DL * KER; idx += NTHR) cw[idx] = conv_w[bid * (DL * KER) + idx];
        for (int idx = tid; idx < 4 * DL;  idx += NTHR) embS[idx] = emb[idx];
        __syncthreads();
        if (tid < NIV) {
            int i = tid >> 2, v = tid & 3;
            float s = 0.f;
#pragma unroll 16
            for (int d = 0; d < DL; d++) s += embS[v * DL + d] * cw[d * KER + i];
            g_Wc[tid * DC + bid] = s;
        }
    }

    grid_barrier(tid);   // g_Wc complete

    // ======== setup phase 2 (blocks 0..127): U, V, WvWc, w, ob ========
    if (bid < DC) {
        float* wkS = scratch;          float* wqS = scratch + DC;
        float* wvS = scratch + 2 * DC; float* cbS = scratch + 3 * DC;
        for (int idx = tid; idx < DC; idx += NTHR) {
            wkS[idx] = Wk[bid * DC + idx];
            wqS[idx] = Wq[bid * DC + idx];
            wvS[idx] = Wv[bid * DC + idx];
            cbS[idx] = conv_b[idx];
        }
        __syncthreads();
        const float isq = 0.088388347648318447f;  // 1/sqrt(128)
        if (tid < NIV) {
            const float4* wc4 = (const float4*)(g_Wc + tid * DC);
            float su = 0.f, sv = 0.f, sw = 0.f;
#pragma unroll 8
            for (int q = 0; q < DC / 4; q++) {
                float4 f = wc4[q];
                int d = q * 4;
                su += f.x * wkS[d] + f.y * wkS[d + 1] + f.z * wkS[d + 2] + f.w * wkS[d + 3];
                sv += f.x * wqS[d] + f.y * wqS[d + 1] + f.z * wqS[d + 2] + f.w * wqS[d + 3];
                sw += f.x * wvS[d] + f.y * wvS[d + 1] + f.z * wvS[d + 2] + f.w * wvS[d + 3];
            }
            g_U[tid * DC + bid] = su * isq;
            g_V[tid * DC + bid] = sv * (1.0f / (float)LOUT);
            g_WvWc[bid * NIV + tid] = sw;
        } else if (tid == 60) {
            float s = bq[bid];
#pragma unroll 8
            for (int e = 0; e < DC; e++) s += wqS[e] * cbS[e];
            g_w[bid] = s;
        } else if (tid == 61) {
            float s = bv[bid];
#pragma unroll 8
            for (int e = 0; e < DC; e++) s += wvS[e] * cbS[e];
            g_ob[bid] = s;
        }
    }

    grid_barrier(tid);   // setup complete

    // ======== per-batch score table: t = w + V'^T fcnt ; S = U' t ========
    if (tid < DC) {
        float s = g_w[tid];
#pragma unroll 12
        for (int j = 0; j < NIV; j++) s += g_V[j * DC + tid] * fcnt_s[j];
        t_s[tid] = s;
    }
    __syncthreads();
    if (tid < NIV) {
        const float4* u4 = (const float4*)(g_U + tid * DC);
        float s = 0.f;
#pragma unroll 8
        for (int q = 0; q < DC / 4; q++) {
            float4 f = u4[q];
            int e = q * 4;
            s += f.x * t_s[e] + f.y * t_s[e + 1] + f.z * t_s[e + 2] + f.w * t_s[e + 3];
        }
        S_s[tid] = s;
    }
    __syncthreads();

    // ======== chunk tables + per-chunk maxima (=> softmax shift bound) ========
    {
        float m0 = -1e30f, m1 = -1e30f, m2 = -1e30f;
#pragma unroll
        for (int q = 0; q < 6; q++) {
            int idx = tid + q * NTHR;
            int k = idx >> 10, u = idx & 1023;
            int xb = u & 31, yb = u >> 5;
            float s = 0.f;
#pragma unroll
            for (int j = 0; j < 5; j++) {
                int v = ((xb >> j) & 1) | (((yb >> j) & 1) << 1);
                s += S_s[(5 * k + j) * 4 + v];
            }
            Tbl[idx] = s;
            if (q < 2) m0 = fmaxf(m0, s);
            else if (q < 4) m1 = fmaxf(m1, s);
            else m2 = fmaxf(m2, s);
        }
#pragma unroll
        for (int o = 16; o > 0; o >>= 1) {
            m0 = fmaxf(m0, __shfl_xor_sync(0xffffffffu, m0, o));
            m1 = fmaxf(m1, __shfl_xor_sync(0xffffffffu, m1, o));
            m2 = fmaxf(m2, __shfl_xor_sync(0xffffffffu, m2, o));
        }
        if (lane == 0) { wacc[warp][0] = m0; wacc[warp][1] = m1; wacc[warp][2] = m2; }
        __syncthreads();
        if (tid == 0) {
            float a = wacc[0][0], b = wacc[0][1], c = wacc[0][2];
#pragma unroll
            for (int w = 1; w < 16; w++) {
                a = fmaxf(a, wacc[w][0]); b = fmaxf(b, wacc[w][1]); c = fmaxf(c, wacc[w][2]);
            }
            bmax_s = a + b + c;   // upper bound on any score (softmax shift-invariant)
        }
        __syncthreads();
    }
    const float bmax = bmax_s;

    // ======== single e-pass: 8 masked positions/thread, e cached in regs ========
    const int base = tid * 8;
    const int wi = base >> 5;
    const int sh0 = base & 31;
    unsigned x0 = Xs[wi], x1 = Xs[wi + 1];
    unsigned y0 = Ys[wi], y1 = Ys[wi + 1];

    float e[8];
    unsigned ub[8];           // packed: bx (15b) | by<<15 (15b)
    float accE = 0.f;
#pragma unroll
    for (int j = 0; j < 8; j++) {
        int sh = sh0 + j;
        unsigned bx = __funnelshift_r(x0, x1, sh) & 0x7FFFu;
        unsigned by = __funnelshift_r(y0, y1, sh) & 0x7FFFu;
        ub[j] = bx | (by << 15);
        int u0 = (bx & 31) | ((by & 31) << 5);
        int u1 = ((bx >> 5) & 31) | (((by >> 5) & 31) << 5);
        int u2 = ((bx >> 10) & 31) | (((by >> 10) & 31) << 5);
        float s = Tbl[u0] + Tbl[1024 + u1] + Tbl[2048 + u2];
        float ev = __expf(s - bmax);
        ev = (base + j < LOUT) ? ev : 0.f;
        e[j] = ev;
        accE += ev;
    }
#pragma unroll
    for (int o = 16; o > 0; o >>= 1) accE += __shfl_xor_sync(0xffffffffu, accE, o);
    if (lane == 0) red_s[warp] = accE;

    // ======== 3 accumulation passes (register-only, no LDS, no exp) ========
#pragma unroll 1
    for (int k = 0; k < 3; k++) {
        float acc[15];
#pragma unroll
        for (int j = 0; j < 15; j++) acc[j] = 0.f;
#pragma unroll
        for (int j = 0; j < 8; j++) {
            unsigned xb = (ub[j] >> (5 * k)) & 31u;
            unsigned yb = (ub[j] >> (15 + 5 * k)) & 31u;
            unsigned xy = xb & yb;
            float ev = e[j];
#pragma unroll
            for (int jj = 0; jj < 5; jj++) {
                acc[jj]      += ((xb >> jj) & 1u) ? ev : 0.f;
                acc[5 + jj]  += ((yb >> jj) & 1u) ? ev : 0.f;
                acc[10 + jj] += ((xy >> jj) & 1u) ? ev : 0.f;
            }
        }
#pragma unroll
        for (int j = 0; j < 15; j++) {
            float v = acc[j];
#pragma unroll
            for (int o = 16; o > 0; o >>= 1) v += __shfl_xor_sync(0xffffffffu, v, o);
            if (lane == 0) wacc[warp][j] = v;
        }
        __syncthreads();
        if (tid < 15) {
            float s = 0.f;
#pragma unroll
            for (int w = 0; w < 16; w++) s += wacc[w][tid];
            int jj = tid % 5, i = 5 * k + jj;
            int dest = (tid < 5) ? (1 + i) : (tid < 10) ? (16 + i) : (31 + i);
            fin[dest] = s;
        } else if (tid == 15 && k == 0) {
            float s = 0.f;
#pragma unroll
            for (int w = 0; w < 16; w++) s += red_s[w];
            fin[0] = s;   // E
        }
        __syncthreads();
    }

    // ---- A[i][v] from (E, Ex, Ey, Exy) ----
    if (tid < NIV) {
        int i = tid >> 2, v = tid & 3;
        float E = fin[0], Ex = fin[1 + i], Ey = fin[16 + i], Exy = fin[31 + i];
        A_s[tid] = (v == 3) ? Exy
                 : (v == 1) ? (Ex - Exy)
                 : (v == 2) ? (Ey - Exy)
                 : (E - Ex - Ey + Exy);
    }
    __syncthreads();

    // ---- out[c] = ob[c] + (WvWc*A)[c]/E ----
    if (tid < DC) {
        const float4* w4 = (const float4*)(g_WvWc + tid * NIV);
        float s = 0.f;
#pragma unroll
        for (int q = 0; q < NIV / 4; q++) {
            float4 f = w4[q];
            int j = q * 4;
            s += f.x * A_s[j] + f.y * A_s[j + 1] + f.z * A_s[j + 2] + f.w * A_s[j + 3];
        }
        out[(size_t)bid * DC + tid] = g_ob[tid] + s / fin[0];
    }
}

// ---------------- launch: ONE kernel ----------------
// Inputs: tokens, emb, conv_w, conv_b, Wq, bq, Wk, bk, Wv, bv  (bk drops out of softmax)
extern "C" void kernel_launch(void* const* d_in, const int* in_sizes, int n_in,
                              void* d_out, int out_size) {
    const int*   tokens = (const int*)  d_in[0];
    const float* emb    = (const float*)d_in[1];
    const float* conv_w = (const float*)d_in[2];
    const float* conv_b = (const float*)d_in[3];
    const float* Wq     = (const float*)d_in[4];
    const float* bq     = (const float*)d_in[5];
    const float* Wk     = (const float*)d_in[6];
    const float* Wv     = (const float*)d_in[8];
    const float* bv     = (const float*)d_in[9];
    float*       out    = (float*)d_out;

    seq_all<<<NBATCH, NTHR>>>(tokens, emb, conv_w, conv_b, Wq, bq, Wk, Wv, bv, out);
}

// round 7
// speedup vs baseline: 1.9469x; 1.1062x over previous
#include <cuda_runtime.h>
#include <cuda_bf16.h>

#define NBATCH 256
#define LSEQ   4096
#define KER    15
#define LOUT   (LSEQ - KER + 1)   // 4082
#define DL     64
#define DC     128
#define NIV    (KER * 4)          // 60
#define NTHR   256

// ---------------- device scratch (rewritten every launch) ----------------
__device__ __align__(16) float g_Wc[NIV * DC];     // Wc[iv][c]
__device__ __align__(16) float g_U[NIV * DC];      // isq * Wc * Wk^T
__device__ __align__(16) float g_V[NIV * DC];      // (Wc * Wq^T) / LOUT
__device__ __align__(16) float g_WvWc[DC * NIV];   // Wv * Wc^T
__device__ __align__(16) float g_w[DC];            // bq + Wq*conv_b
__device__ __align__(16) float g_ob[DC];           // bv + Wv*conv_b

// ---------------- software grid barrier (sense-reversing) ----------------
__device__ unsigned g_barc = 0;
__device__ volatile unsigned g_sense = 0;

__device__ __forceinline__ void grid_barrier(int tid) {
    __syncthreads();
    if (tid == 0) {
        unsigned s = g_sense;
        __threadfence();
        unsigned old = atomicAdd(&g_barc, 1u);
        if (old == NBATCH - 1) {
            g_barc = 0;
            __threadfence();
            g_sense = s ^ 1u;
        } else {
            while (g_sense == s) { }
        }
        __threadfence();
    }
    __syncthreads();
}

// 256 blocks x 256 threads, <=128 regs, ~16KB smem => 2 blocks/SM => 296 slots,
// all 256 blocks co-resident => grid barrier safe.
__global__ void __launch_bounds__(NTHR, 2)
seq_all(const int*   __restrict__ tokens,
        const float* __restrict__ emb,   const float* __restrict__ conv_w,
        const float* __restrict__ conv_b,
        const float* __restrict__ Wq,    const float* __restrict__ bq,
        const float* __restrict__ Wk,    const float* __restrict__ Wv,
        const float* __restrict__ bv,    float* __restrict__ out) {
    __shared__ float Tbl[3072];                 // chunk tables; aliased setup scratch
    __shared__ unsigned int Xs[129], Ys[129];
    __shared__ float t_s[DC];
    __shared__ float S_s[NIV], fcnt_s[NIV], A_s[NIV];
    __shared__ float wacc[8][48];               // 8 warps x 46 (padded)
    __shared__ float fin[46];                   // [0..14]=Ex, [15..29]=Ey, [30..44]=Exy, [45]=E
    __shared__ int hist_s[4];
    __shared__ float bmax_s;

    const int tid = threadIdx.x, lane = tid & 31, warp = tid >> 5;
    const int bid = blockIdx.x;
    float* scratch = Tbl;

    if (tid < 4) hist_s[tid] = 0;
    if (tid == 0) { Xs[128] = 0u; Ys[128] = 0u; }
    __syncthreads();

    // ======== prologue: tokens -> bitplanes + histogram ========
    const int* trow = tokens + (size_t)bid * LSEQ;
    int tv[16];
#pragma unroll
    for (int m = 0; m < 16; m++) tv[m] = trow[m * NTHR + warp * 32 + lane];
    int n0 = 0, n1 = 0, n2 = 0, n3 = 0;
#pragma unroll
    for (int m = 0; m < 16; m++) {
        unsigned b0 = __ballot_sync(0xffffffffu, tv[m] & 1);
        unsigned b1 = __ballot_sync(0xffffffffu, tv[m] & 2);
        if (lane == 0) {
            Xs[m * 8 + warp] = b0; Ys[m * 8 + warp] = b1;
            int c3 = __popc(b0 & b1);
            int c1 = __popc(b0) - c3;
            int c2 = __popc(b1) - c3;
            n3 += c3; n1 += c1; n2 += c2; n0 += 32 - c1 - c2 - c3;
        }
    }
    if (lane == 0) {
        atomicAdd(&hist_s[0], n0); atomicAdd(&hist_s[1], n1);
        atomicAdd(&hist_s[2], n2); atomicAdd(&hist_s[3], n3);
    }
    __syncthreads();

#define TOK_AT(p) ((int)(((Xs[(p) >> 5] >> ((p) & 31)) & 1u) | (((Ys[(p) >> 5] >> ((p) & 31)) & 1u) << 1)))

    if (tid < NIV) {   // sliding-window counts
        int i = tid >> 2, v = tid & 3;
        int cnt = hist_s[v];
        for (int p = 0; p < i; p++) cnt -= (TOK_AT(p) == v);
        for (int p = i + LOUT; p < LSEQ; p++) cnt -= (TOK_AT(p) == v);
        fcnt_s[tid] = (float)cnt;
    }

    // ======== setup phase 1 (blocks 0..127): Wc column c=bid ========
    if (bid < DC) {
        float* cw   = scratch;          // 960
        float* embS = scratch + 960;    // 256
        for (int idx = tid; idx < DL * KER; idx += NTHR) cw[idx] = conv_w[bid * (DL * KER) + idx];
        for (int idx = tid; idx < 4 * DL;  idx += NTHR) embS[idx] = emb[idx];
        __syncthreads();
        if (tid < NIV) {
            int i = tid >> 2, v = tid & 3;
            float s = 0.f;
#pragma unroll 16
            for (int d = 0; d < DL; d++) s += embS[v * DL + d] * cw[d * KER + i];
            g_Wc[tid * DC + bid] = s;
        }
    }

    grid_barrier(tid);   // g_Wc complete

    // ======== setup phase 2 (blocks 0..127): U, V, WvWc, w, ob ========
    if (bid < DC) {
        float* wkS = scratch;          float* wqS = scratch + DC;
        float* wvS = scratch + 2 * DC; float* cbS = scratch + 3 * DC;
        for (int idx = tid; idx < DC; idx += NTHR) {
            wkS[idx] = Wk[bid * DC + idx];
            wqS[idx] = Wq[bid * DC + idx];
            wvS[idx] = Wv[bid * DC + idx];
            cbS[idx] = conv_b[idx];
        }
        __syncthreads();
        const float isq = 0.088388347648318447f;  // 1/sqrt(128)
        if (tid < NIV) {
            const float4* wc4 = (const float4*)(g_Wc + tid * DC);
            float su = 0.f, sv = 0.f, sw = 0.f;
#pragma unroll 8
            for (int q = 0; q < DC / 4; q++) {
                float4 f = wc4[q];
                int d = q * 4;
                su += f.x * wkS[d] + f.y * wkS[d + 1] + f.z * wkS[d + 2] + f.w * wkS[d + 3];
                sv += f.x * wqS[d] + f.y * wqS[d + 1] + f.z * wqS[d + 2] + f.w * wqS[d + 3];
                sw += f.x * wvS[d] + f.y * wvS[d + 1] + f.z * wvS[d + 2] + f.w * wvS[d + 3];
            }
            g_U[tid * DC + bid] = su * isq;
            g_V[tid * DC + bid] = sv * (1.0f / (float)LOUT);
            g_WvWc[bid * NIV + tid] = sw;
        } else if (tid == 60) {
            float s = bq[bid];
#pragma unroll 8
            for (int e = 0; e < DC; e++) s += wqS[e] * cbS[e];
            g_w[bid] = s;
        } else if (tid == 61) {
            float s = bv[bid];
#pragma unroll 8
            for (int e = 0; e < DC; e++) s += wvS[e] * cbS[e];
            g_ob[bid] = s;
        }
    }

    grid_barrier(tid);   // setup complete

    // ======== per-batch score table: t = w + V'^T fcnt ; S = U' t ========
    if (tid < DC) {
        float s = g_w[tid];
#pragma unroll 12
        for (int j = 0; j < NIV; j++) s += g_V[j * DC + tid] * fcnt_s[j];
        t_s[tid] = s;
    }
    __syncthreads();
    if (tid < NIV) {
        const float4* u4 = (const float4*)(g_U + tid * DC);
        float s = 0.f;
#pragma unroll 8
        for (int q = 0; q < DC / 4; q++) {
            float4 f = u4[q];
            int e = q * 4;
            s += f.x * t_s[e] + f.y * t_s[e + 1] + f.z * t_s[e + 2] + f.w * t_s[e + 3];
        }
        S_s[tid] = s;
    }
    __syncthreads();

    // ======== chunk tables + per-chunk maxima (=> softmax shift bound) ========
    {
        float m0 = -1e30f, m1 = -1e30f, m2 = -1e30f;
#pragma unroll
        for (int q = 0; q < 12; q++) {
            int idx = tid + q * NTHR;
            int k = idx >> 10, u = idx & 1023;
            int xb = u & 31, yb = u >> 5;
            float s = 0.f;
#pragma unroll
            for (int j = 0; j < 5; j++) {
                int v = ((xb >> j) & 1) | (((yb >> j) & 1) << 1);
                s += S_s[(5 * k + j) * 4 + v];
            }
            Tbl[idx] = s;
            if (q < 4) m0 = fmaxf(m0, s);
            else if (q < 8) m1 = fmaxf(m1, s);
            else m2 = fmaxf(m2, s);
        }
#pragma unroll
        for (int o = 16; o > 0; o >>= 1) {
            m0 = fmaxf(m0, __shfl_xor_sync(0xffffffffu, m0, o));
            m1 = fmaxf(m1, __shfl_xor_sync(0xffffffffu, m1, o));
            m2 = fmaxf(m2, __shfl_xor_sync(0xffffffffu, m2, o));
        }
        if (lane == 0) { wacc[warp][0] = m0; wacc[warp][1] = m1; wacc[warp][2] = m2; }
        __syncthreads();
        if (tid == 0) {
            float a = wacc[0][0], b = wacc[0][1], c = wacc[0][2];
#pragma unroll
            for (int w = 1; w < 8; w++) {
                a = fmaxf(a, wacc[w][0]); b = fmaxf(b, wacc[w][1]); c = fmaxf(c, wacc[w][2]);
            }
            bmax_s = a + b + c;   // upper bound on any score (softmax shift-invariant)
        }
        __syncthreads();
    }
    const float bmax = bmax_s;

    // ======== ONE fused pass: 16 positions/thread, 45 resident accumulators ========
    const int base = tid * 16;                 // 256*16 = 4096 covers LOUT
    const int wi = base >> 5;                  // tid/2
    const int sh0 = base & 31;                 // 0 or 16
    const unsigned x0 = Xs[wi], x1 = Xs[wi + 1];
    const unsigned y0 = Ys[wi], y1 = Ys[wi + 1];

    float acc[45];
#pragma unroll
    for (int j = 0; j < 45; j++) acc[j] = 0.f;
    float accE = 0.f;

#pragma unroll 4
    for (int j = 0; j < 16; j++) {
        int sh = sh0 + j;
        unsigned bx = __funnelshift_r(x0, x1, sh) & 0x7FFFu;
        unsigned by = __funnelshift_r(y0, y1, sh) & 0x7FFFu;
        int u0 = (bx & 31) | ((by & 31) << 5);
        int u1 = ((bx >> 5) & 31) | (((by >> 5) & 31) << 5);
        int u2 = ((bx >> 10) & 31) | (((by >> 10) & 31) << 5);
        float s = Tbl[u0] + Tbl[1024 + u1] + Tbl[2048 + u2];
        float ev = __expf(s - bmax);
        ev = (base + j < LOUT) ? ev : 0.f;
        accE += ev;
        unsigned bxy = bx & by;
#pragma unroll
        for (int i = 0; i < 15; i++) {
            acc[i]      += ((bx  >> i) & 1u) ? ev : 0.f;
            acc[15 + i] += ((by  >> i) & 1u) ? ev : 0.f;
            acc[30 + i] += ((bxy >> i) & 1u) ? ev : 0.f;
        }
    }

    // ======== reduce 46 values across 8 warps ========
#pragma unroll
    for (int j = 0; j < 45; j++) {
        float v = acc[j];
#pragma unroll
        for (int o = 16; o > 0; o >>= 1) v += __shfl_xor_sync(0xffffffffu, v, o);
        if (lane == 0) wacc[warp][j] = v;
    }
#pragma unroll
    for (int o = 16; o > 0; o >>= 1) accE += __shfl_xor_sync(0xffffffffu, accE, o);
    if (lane == 0) wacc[warp][45] = accE;
    __syncthreads();
    if (tid < 46) {
        float s = 0.f;
#pragma unroll
        for (int w = 0; w < 8; w++) s += wacc[w][tid];
        fin[tid] = s;
    }
    __syncthreads();

    // ---- A[i][v] from (E, Ex, Ey, Exy) ----
    if (tid < NIV) {
        int i = tid >> 2, v = tid & 3;
        float E = fin[45], Ex = fin[i], Ey = fin[15 + i], Exy = fin[30 + i];
        A_s[tid] = (v == 3) ? Exy
                 : (v == 1) ? (Ex - Exy)
                 : (v == 2) ? (Ey - Exy)
                 : (E - Ex - Ey + Exy);
    }
    __syncthreads();

    // ---- out[c] = ob[c] + (WvWc*A)[c]/E ----
    if (tid < DC) {
        const float4* w4 = (const float4*)(g_WvWc + tid * NIV);
        float s = 0.f;
#pragma unroll
        for (int q = 0; q < NIV / 4; q++) {
            float4 f = w4[q];
            int j = q * 4;
            s += f.x * A_s[j] + f.y * A_s[j + 1] + f.z * A_s[j + 2] + f.w * A_s[j + 3];
        }
        out[(size_t)bid * DC + tid] = g_ob[tid] + s / fin[45];
    }
}

// ---------------- launch: ONE kernel ----------------
// Inputs: tokens, emb, conv_w, conv_b, Wq, bq, Wk, bk, Wv, bv  (bk drops out of softmax)
extern "C" void kernel_launch(void* const* d_in, const int* in_sizes, int n_in,
                              void* d_out, int out_size) {
    const int*   tokens = (const int*)  d_in[0];
    const float* emb    = (const float*)d_in[1];
    const float* conv_w = (const float*)d_in[2];
    const float* conv_b = (const float*)d_in[3];
    const float* Wq     = (const float*)d_in[4];
    const float* bq     = (const float*)d_in[5];
    const float* Wk     = (const float*)d_in[6];
    const float* Wv     = (const float*)d_in[8];
    const float* bv     = (const float*)d_in[9];
    float*       out    = (float*)d_out;

    seq_all<<<NBATCH, NTHR>>>(tokens, emb, conv_w, conv_b, Wq, bq, Wk, Wv, bv, out);
}

// round 8
// speedup vs baseline: 1.9908x; 1.0225x over previous
#include <cuda_runtime.h>
#include <cuda_bf16.h>

#define NBATCH 256
#define LSEQ   4096
#define KER    15
#define LOUT   (LSEQ - KER + 1)   // 4082
#define DL     64
#define DC     128
#define NIV    (KER * 4)          // 60
#define NTHR   256

// ---------------- device scratch (rewritten every launch) ----------------
__device__ __align__(16) float g_Wc[NIV * DC];     // Wc[iv][c]
__device__ __align__(16) float g_U[NIV * DC];      // isq * Wc * Wk^T
__device__ __align__(16) float g_V[NIV * DC];      // (Wc * Wq^T) / LOUT
__device__ __align__(16) float g_WvWc[DC * NIV];   // Wv * Wc^T
__device__ __align__(16) float g_w[DC];            // bq + Wq*conv_b
__device__ __align__(16) float g_ob[DC];           // bv + Wv*conv_b

// ---------------- software grid barrier (sense-reversing) ----------------
__device__ unsigned g_barc = 0;
__device__ volatile unsigned g_sense = 0;

__device__ __forceinline__ void grid_barrier(int tid) {
    __syncthreads();
    if (tid == 0) {
        unsigned s = g_sense;
        __threadfence();
        unsigned old = atomicAdd(&g_barc, 1u);
        if (old == NBATCH - 1) {
            g_barc = 0;
            __threadfence();
            g_sense = s ^ 1u;
        } else {
            while (g_sense == s) { }
        }
        __threadfence();
    }
    __syncthreads();
}

// 256 blocks x 256 threads, <=128 regs, ~16KB smem => 2 blocks/SM => all co-resident.
__global__ void __launch_bounds__(NTHR, 2)
seq_all(const int*   __restrict__ tokens,
        const float* __restrict__ emb,   const float* __restrict__ conv_w,
        const float* __restrict__ conv_b,
        const float* __restrict__ Wq,    const float* __restrict__ bq,
        const float* __restrict__ Wk,    const float* __restrict__ Wv,
        const float* __restrict__ bv,    float* __restrict__ out) {
    __shared__ float Tbl[3072];                 // chunk tables; aliased setup scratch
    __shared__ unsigned int Xs[129], Ys[129];
    __shared__ float t_s[DC];
    __shared__ float S_s[NIV], fcnt_s[NIV], A_s[NIV];
    __shared__ float wacc[8][48];
    __shared__ float fin[46];                   // [0..14]=Ex, [15..29]=Ey, [30..44]=Exy, [45]=E
    __shared__ int hist_s[4];
    __shared__ float bmax_s;

    const int tid = threadIdx.x, lane = tid & 31, warp = tid >> 5;
    const int bid = blockIdx.x;
    float* scratch = Tbl;

    if (tid < 4) hist_s[tid] = 0;
    if (tid == 0) { Xs[128] = 0u; Ys[128] = 0u; }
    __syncthreads();

    // ======== prologue: tokens -> bitplanes + histogram (vectorized loads) ========
    const int4* trow4 = (const int4*)(tokens + (size_t)bid * LSEQ);
    int4 tq[4];
#pragma unroll
    for (int m = 0; m < 4; m++) tq[m] = trow4[m * NTHR + warp * 32 + lane];
    int n0 = 0, n1 = 0, n2 = 0, n3 = 0;
#pragma unroll
    for (int m = 0; m < 4; m++) {
        int vv[4] = { tq[m].x, tq[m].y, tq[m].z, tq[m].w };
#pragma unroll
        for (int q = 0; q < 4; q++) {
            unsigned b0 = __ballot_sync(0xffffffffu, vv[q] & 1);
            unsigned b1 = __ballot_sync(0xffffffffu, vv[q] & 2);
            if (lane == 0) {
                // element idx = (m*NTHR + warp*32 + lane)*4 + q ; word = idx_base/32
                int w = (m * NTHR + warp * 32) >> 3;   // *4/32
                Xs[w + q] = b0; Ys[w + q] = b1;        // wait: need interleave-correct mapping
            }
        }
    }
    // NOTE: int4 lane-interleaved ballots do NOT produce contiguous bitplanes.
    // Rebuild properly below from shared tokens instead (correctness first):
    __syncthreads();
    {
        // redo bitplanes correctly: each warp processes contiguous 32-token groups
        int base0 = warp * 32 + lane;   // reuse registers
        (void)base0;
    }
    // --- correct bitplane construction (strided scalar ballots, like R7) ---
    {
        const int* trow = tokens + (size_t)bid * LSEQ;
        n0 = n1 = n2 = n3 = 0;
#pragma unroll
        for (int m = 0; m < 16; m++) {
            int t = trow[m * NTHR + warp * 32 + lane];
            unsigned b0 = __ballot_sync(0xffffffffu, t & 1);
            unsigned b1 = __ballot_sync(0xffffffffu, t & 2);
            if (lane == 0) {
                Xs[m * 8 + warp] = b0; Ys[m * 8 + warp] = b1;
                int c3 = __popc(b0 & b1);
                int c1 = __popc(b0) - c3;
                int c2 = __popc(b1) - c3;
                n3 += c3; n1 += c1; n2 += c2; n0 += 32 - c1 - c2 - c3;
            }
        }
        if (lane == 0) {
            atomicAdd(&hist_s[0], n0); atomicAdd(&hist_s[1], n1);
            atomicAdd(&hist_s[2], n2); atomicAdd(&hist_s[3], n3);
        }
    }
    __syncthreads();

#define TOK_AT(p) ((int)(((Xs[(p) >> 5] >> ((p) & 31)) & 1u) | (((Ys[(p) >> 5] >> ((p) & 31)) & 1u) << 1)))

    if (tid < NIV) {   // sliding-window counts
        int i = tid >> 2, v = tid & 3;
        int cnt = hist_s[v];
        for (int p = 0; p < i; p++) cnt -= (TOK_AT(p) == v);
        for (int p = i + LOUT; p < LSEQ; p++) cnt -= (TOK_AT(p) == v);
        fcnt_s[tid] = (float)cnt;
    }

    // ======== setup phase 1 (blocks 0..127): Wc column c=bid ========
    if (bid < DC) {
        float* cw   = scratch;          // 960
        float* embS = scratch + 960;    // 256
        for (int idx = tid; idx < DL * KER; idx += NTHR) cw[idx] = conv_w[bid * (DL * KER) + idx];
        for (int idx = tid; idx < 4 * DL;  idx += NTHR) embS[idx] = emb[idx];
        __syncthreads();
        if (tid < NIV) {
            int i = tid >> 2, v = tid & 3;
            float s = 0.f;
#pragma unroll 16
            for (int d = 0; d < DL; d++) s += embS[v * DL + d] * cw[d * KER + i];
            g_Wc[tid * DC + bid] = s;
        }
    }

    grid_barrier(tid);   // g_Wc complete

    // ======== setup phase 2 (blocks 0..127): U, V, WvWc, w, ob ========
    if (bid < DC) {
        float* wkS = scratch;          float* wqS = scratch + DC;
        float* wvS = scratch + 2 * DC; float* cbS = scratch + 3 * DC;
        for (int idx = tid; idx < DC; idx += NTHR) {
            wkS[idx] = Wk[bid * DC + idx];
            wqS[idx] = Wq[bid * DC + idx];
            wvS[idx] = Wv[bid * DC + idx];
            cbS[idx] = conv_b[idx];
        }
        __syncthreads();
        const float isq = 0.088388347648318447f;  // 1/sqrt(128)
        if (tid < NIV) {
            const float4* wc4 = (const float4*)(g_Wc + tid * DC);
            float su = 0.f, sv = 0.f, sw = 0.f;
#pragma unroll 8
            for (int q = 0; q < DC / 4; q++) {
                float4 f = wc4[q];
                int d = q * 4;
                su += f.x * wkS[d] + f.y * wkS[d + 1] + f.z * wkS[d + 2] + f.w * wkS[d + 3];
                sv += f.x * wqS[d] + f.y * wqS[d + 1] + f.z * wqS[d + 2] + f.w * wqS[d + 3];
                sw += f.x * wvS[d] + f.y * wvS[d + 1] + f.z * wvS[d + 2] + f.w * wvS[d + 3];
            }
            g_U[tid * DC + bid] = su * isq;
            g_V[tid * DC + bid] = sv * (1.0f / (float)LOUT);
            g_WvWc[bid * NIV + tid] = sw;
        } else if (tid == 60) {
            float s = bq[bid];
#pragma unroll 8
            for (int e = 0; e < DC; e++) s += wqS[e] * cbS[e];
            g_w[bid] = s;
        } else if (tid == 61) {
            float s = bv[bid];
#pragma unroll 8
            for (int e = 0; e < DC; e++) s += wvS[e] * cbS[e];
            g_ob[bid] = s;
        }
    }

    grid_barrier(tid);   // setup complete

    // ======== per-batch score table: t = w + V'^T fcnt ; S = U' t ========
    if (tid < DC) {
        float s = g_w[tid];
#pragma unroll 12
        for (int j = 0; j < NIV; j++) s += g_V[j * DC + tid] * fcnt_s[j];
        t_s[tid] = s;
    }
    __syncthreads();
    if (tid < NIV) {
        const float4* u4 = (const float4*)(g_U + tid * DC);
        float s = 0.f;
#pragma unroll 8
        for (int q = 0; q < DC / 4; q++) {
            float4 f = u4[q];
            int e = q * 4;
            s += f.x * t_s[e] + f.y * t_s[e + 1] + f.z * t_s[e + 2] + f.w * t_s[e + 3];
        }
        S_s[tid] = s;
    }
    __syncthreads();

    // ======== chunk tables + per-chunk maxima (softmax shift bound) ========
    {
        float m0 = -1e30f, m1 = -1e30f, m2 = -1e30f;
#pragma unroll
        for (int q = 0; q < 12; q++) {
            int idx = tid + q * NTHR;
            int k = idx >> 10, u = idx & 1023;
            int xb = u & 31, yb = u >> 5;
            float s = 0.f;
#pragma unroll
            for (int j = 0; j < 5; j++) {
                int v = ((xb >> j) & 1) | (((yb >> j) & 1) << 1);
                s += S_s[(5 * k + j) * 4 + v];
            }
            Tbl[idx] = s;
            if (q < 4) m0 = fmaxf(m0, s);
            else if (q < 8) m1 = fmaxf(m1, s);
            else m2 = fmaxf(m2, s);
        }
#pragma unroll
        for (int o = 16; o > 0; o >>= 1) {
            m0 = fmaxf(m0, __shfl_xor_sync(0xffffffffu, m0, o));
            m1 = fmaxf(m1, __shfl_xor_sync(0xffffffffu, m1, o));
            m2 = fmaxf(m2, __shfl_xor_sync(0xffffffffu, m2, o));
        }
        if (lane == 0) { wacc[warp][0] = m0; wacc[warp][1] = m1; wacc[warp][2] = m2; }
        __syncthreads();
        if (tid == 0) {
            float a = wacc[0][0], b = wacc[0][1], c = wacc[0][2];
#pragma unroll
            for (int w = 1; w < 8; w++) {
                a = fmaxf(a, wacc[w][0]); b = fmaxf(b, wacc[w][1]); c = fmaxf(c, wacc[w][2]);
            }
            bmax_s = a + b + c;
        }
        __syncthreads();
    }
    const float bmax = bmax_s;

    // ======== ONE fused pass: 16 positions/thread, 45 resident accumulators ========
    const int base = tid * 16;
    const int wi = base >> 5;
    const int sh0 = base & 31;
    const unsigned x0 = Xs[wi], x1 = Xs[wi + 1];
    const unsigned y0 = Ys[wi], y1 = Ys[wi + 1];

    float acc[45];
#pragma unroll
    for (int j = 0; j < 45; j++) acc[j] = 0.f;
    float accE = 0.f;

#pragma unroll 2
    for (int j = 0; j < 16; j++) {
        int sh = sh0 + j;
        unsigned bx = __funnelshift_r(x0, x1, sh);
        unsigned by = __funnelshift_r(y0, y1, sh);
        int u0 = (bx & 31) | ((by & 31) << 5);
        int u1 = ((bx >> 5) & 31) | (((by >> 5) & 31) << 5);
        int u2 = ((bx >> 10) & 31) | (((by >> 10) & 31) << 5);
        float s = Tbl[u0] + Tbl[1024 + u1] + Tbl[2048 + u2];
        float ev = __expf(s - bmax);
        ev = (base + j < LOUT) ? ev : 0.f;
        accE += ev;
        unsigned bxy = bx & by;
#pragma unroll
        for (int i = 0; i < 15; i++) {
            acc[i]      += (bx  & (1u << i)) ? ev : 0.f;
            acc[15 + i] += (by  & (1u << i)) ? ev : 0.f;
            acc[30 + i] += (bxy & (1u << i)) ? ev : 0.f;
        }
    }

    // ======== reduce 46 values across 8 warps ========
#pragma unroll
    for (int j = 0; j < 45; j++) {
        float v = acc[j];
#pragma unroll
        for (int o = 16; o > 0; o >>= 1) v += __shfl_xor_sync(0xffffffffu, v, o);
        if (lane == 0) wacc[warp][j] = v;
    }
#pragma unroll
    for (int o = 16; o > 0; o >>= 1) accE += __shfl_xor_sync(0xffffffffu, accE, o);
    if (lane == 0) wacc[warp][45] = accE;
    __syncthreads();
    if (tid < 46) {
        float s = 0.f;
#pragma unroll
        for (int w = 0; w < 8; w++) s += wacc[w][tid];
        fin[tid] = s;
    }
    __syncthreads();

    // ---- A[i][v] from (E, Ex, Ey, Exy) ----
    if (tid < NIV) {
        int i = tid >> 2, v = tid & 3;
        float E = fin[45], Ex = fin[i], Ey = fin[15 + i], Exy = fin[30 + i];
        A_s[tid] = (v == 3) ? Exy
                 : (v == 1) ? (Ex - Exy)
                 : (v == 2) ? (Ey - Exy)
                 : (E - Ex - Ey + Exy);
    }
    __syncthreads();

    // ---- out[c] = ob[c] + (WvWc*A)[c]/E ----
    if (tid < DC) {
        const float4* w4 = (const float4*)(g_WvWc + tid * NIV);
        float s = 0.f;
#pragma unroll
        for (int q = 0; q < NIV / 4; q++) {
            float4 f = w4[q];
            int j = q * 4;
            s += f.x * A_s[j] + f.y * A_s[j + 1] + f.z * A_s[j + 2] + f.w * A_s[j + 3];
        }
        out[(size_t)bid * DC + tid] = g_ob[tid] + s / fin[45];
    }
}

// ---------------- launch: ONE kernel ----------------
// Inputs: tokens, emb, conv_w, conv_b, Wq, bq, Wk, bk, Wv, bv  (bk drops out of softmax)
extern "C" void kernel_launch(void* const* d_in, const int* in_sizes, int n_in,
                              void* d_out, int out_size) {
    const int*   tokens = (const int*)  d_in[0];
    const float* emb    = (const float*)d_in[1];
    const float* conv_w = (const float*)d_in[2];
    const float* conv_b = (const float*)d_in[3];
    const float* Wq     = (const float*)d_in[4];
    const float* bq     = (const float*)d_in[5];
    const float* Wk     = (const float*)d_in[6];
    const float* Wv     = (const float*)d_in[8];
    const float* bv     = (const float*)d_in[9];
    float*       out    = (float*)d_out;

    seq_all<<<NBATCH, NTHR>>>(tokens, emb, conv_w, conv_b, Wq, bq, Wk, Wv, bv, out);
}

// round 9
// speedup vs baseline: 1.9928x; 1.0010x over previous
#include <cuda_runtime.h>
#include <cuda_bf16.h>

#define NBATCH 256
#define LSEQ   4096
#define KER    15
#define LOUT   (LSEQ - KER + 1)   // 4082
#define DL     64
#define DC     128
#define NIV    (KER * 4)          // 60
#define NTHR   256

// ---------------- device scratch (rewritten every launch) ----------------
__device__ __align__(16) float g_Wc[NIV * DC];     // Wc[iv][c]
__device__ __align__(16) float g_U[NIV * DC];      // isq * Wc * Wk^T
__device__ __align__(16) float g_V[NIV * DC];      // (Wc * Wq^T) / LOUT
__device__ __align__(16) float g_WvWc[DC * NIV];   // Wv * Wc^T
__device__ __align__(16) float g_w[DC];            // bq + Wq*conv_b
__device__ __align__(16) float g_ob[DC];           // bv + Wv*conv_b

// ---------------- software grid barrier (sense-reversing) ----------------
__device__ unsigned g_barc = 0;
__device__ volatile unsigned g_sense = 0;

__device__ __forceinline__ void grid_barrier(int tid) {
    __syncthreads();
    if (tid == 0) {
        unsigned s = g_sense;
        __threadfence();
        unsigned old = atomicAdd(&g_barc, 1u);
        if (old == NBATCH - 1) {
            g_barc = 0;
            __threadfence();
            g_sense = s ^ 1u;
        } else {
            while (g_sense == s) { }
        }
        __threadfence();
    }
    __syncthreads();
}

// 256 blocks x 256 threads, <=128 regs, ~33KB smem => 2 blocks/SM => all co-resident.
__global__ void __launch_bounds__(NTHR, 2)
seq_all(const int*   __restrict__ tokens,
        const float* __restrict__ emb,   const float* __restrict__ conv_w,
        const float* __restrict__ conv_b,
        const float* __restrict__ Wq,    const float* __restrict__ bq,
        const float* __restrict__ Wk,    const float* __restrict__ Wv,
        const float* __restrict__ bv,    float* __restrict__ out) {
    __shared__ float Tbl[3072];                 // chunk tables; aliased setup scratch
    __shared__ float e_s[4096];                 // 16 KB: cached exp values
    __shared__ unsigned int Xs[129], Ys[129];
    __shared__ float t_s[DC];
    __shared__ float S_s[NIV], fcnt_s[NIV], A_s[NIV];
    __shared__ float wacc[8][48];
    __shared__ float fin[46];                   // [0..14]=Ex, [15..29]=Ey, [30..44]=Exy, [45]=E
    __shared__ int hist_s[4];
    __shared__ float bmax_s;

    const int tid = threadIdx.x, lane = tid & 31, warp = tid >> 5;
    const int bid = blockIdx.x;
    float* scratch = Tbl;

    if (tid < 4) hist_s[tid] = 0;
    if (tid == 0) { Xs[128] = 0u; Ys[128] = 0u; }
    __syncthreads();

    // ======== prologue: tokens -> bitplanes + histogram ========
    {
        const int* trow = tokens + (size_t)bid * LSEQ;
        int n0 = 0, n1 = 0, n2 = 0, n3 = 0;
#pragma unroll
        for (int m = 0; m < 16; m++) {
            int t = trow[m * NTHR + warp * 32 + lane];
            unsigned b0 = __ballot_sync(0xffffffffu, t & 1);
            unsigned b1 = __ballot_sync(0xffffffffu, t & 2);
            if (lane == 0) {
                Xs[m * 8 + warp] = b0; Ys[m * 8 + warp] = b1;
                int c3 = __popc(b0 & b1);
                int c1 = __popc(b0) - c3;
                int c2 = __popc(b1) - c3;
                n3 += c3; n1 += c1; n2 += c2; n0 += 32 - c1 - c2 - c3;
            }
        }
        if (lane == 0) {
            atomicAdd(&hist_s[0], n0); atomicAdd(&hist_s[1], n1);
            atomicAdd(&hist_s[2], n2); atomicAdd(&hist_s[3], n3);
        }
    }
    __syncthreads();

#define TOK_AT(p) ((int)(((Xs[(p) >> 5] >> ((p) & 31)) & 1u) | (((Ys[(p) >> 5] >> ((p) & 31)) & 1u) << 1)))

    if (tid < NIV) {   // sliding-window counts
        int i = tid >> 2, v = tid & 3;
        int cnt = hist_s[v];
        for (int p = 0; p < i; p++) cnt -= (TOK_AT(p) == v);
        for (int p = i + LOUT; p < LSEQ; p++) cnt -= (TOK_AT(p) == v);
        fcnt_s[tid] = (float)cnt;
    }

    // ======== setup phase 1 (blocks 0..127): Wc column c=bid ========
    if (bid < DC) {
        float* cw   = scratch;          // 960
        float* embS = scratch + 960;    // 256
        for (int idx = tid; idx < DL * KER; idx += NTHR) cw[idx] = conv_w[bid * (DL * KER) + idx];
        for (int idx = tid; idx < 4 * DL;  idx += NTHR) embS[idx] = emb[idx];
        __syncthreads();
        if (tid < NIV) {
            int i = tid >> 2, v = tid & 3;
            float s = 0.f;
#pragma unroll 16
            for (int d = 0; d < DL; d++) s += embS[v * DL + d] * cw[d * KER + i];
            g_Wc[tid * DC + bid] = s;
        }
    }

    grid_barrier(tid);   // g_Wc complete

    // ======== setup phase 2 (blocks 0..127): U, V, WvWc, w, ob ========
    if (bid < DC) {
        float* wkS = scratch;          float* wqS = scratch + DC;
        float* wvS = scratch + 2 * DC; float* cbS = scratch + 3 * DC;
        for (int idx = tid; idx < DC; idx += NTHR) {
            wkS[idx] = Wk[bid * DC + idx];
            wqS[idx] = Wq[bid * DC + idx];
            wvS[idx] = Wv[bid * DC + idx];
            cbS[idx] = conv_b[idx];
        }
        __syncthreads();
        const float isq = 0.088388347648318447f;  // 1/sqrt(128)
        if (tid < NIV) {
            const float4* wc4 = (const float4*)(g_Wc + tid * DC);
            float su = 0.f, sv = 0.f, sw = 0.f;
#pragma unroll 8
            for (int q = 0; q < DC / 4; q++) {
                float4 f = wc4[q];
                int d = q * 4;
                su += f.x * wkS[d] + f.y * wkS[d + 1] + f.z * wkS[d + 2] + f.w * wkS[d + 3];
                sv += f.x * wqS[d] + f.y * wqS[d + 1] + f.z * wqS[d + 2] + f.w * wqS[d + 3];
                sw += f.x * wvS[d] + f.y * wvS[d + 1] + f.z * wvS[d + 2] + f.w * wvS[d + 3];
            }
            g_U[tid * DC + bid] = su * isq;
            g_V[tid * DC + bid] = sv * (1.0f / (float)LOUT);
            g_WvWc[bid * NIV + tid] = sw;
        } else if (tid == 60) {
            float s = bq[bid];
#pragma unroll 8
            for (int e = 0; e < DC; e++) s += wqS[e] * cbS[e];
            g_w[bid] = s;
        } else if (tid == 61) {
            float s = bv[bid];
#pragma unroll 8
            for (int e = 0; e < DC; e++) s += wvS[e] * cbS[e];
            g_ob[bid] = s;
        }
    }

    grid_barrier(tid);   // setup complete

    // ======== per-batch score table: t = w + V'^T fcnt ; S = U' t ========
    if (tid < DC) {
        float s = g_w[tid];
#pragma unroll 12
        for (int j = 0; j < NIV; j++) s += g_V[j * DC + tid] * fcnt_s[j];
        t_s[tid] = s;
    }
    __syncthreads();
    if (tid < NIV) {
        const float4* u4 = (const float4*)(g_U + tid * DC);
        float s = 0.f;
#pragma unroll 8
        for (int q = 0; q < DC / 4; q++) {
            float4 f = u4[q];
            int e = q * 4;
            s += f.x * t_s[e] + f.y * t_s[e + 1] + f.z * t_s[e + 2] + f.w * t_s[e + 3];
        }
        S_s[tid] = s;
    }
    __syncthreads();

    // ======== chunk tables + per-chunk maxima (softmax shift bound) ========
    {
        float m0 = -1e30f, m1 = -1e30f, m2 = -1e30f;
#pragma unroll
        for (int q = 0; q < 12; q++) {
            int idx = tid + q * NTHR;
            int k = idx >> 10, u = idx & 1023;
            int xb = u & 31, yb = u >> 5;
            float s = 0.f;
#pragma unroll
            for (int j = 0; j < 5; j++) {
                int v = ((xb >> j) & 1) | (((yb >> j) & 1) << 1);
                s += S_s[(5 * k + j) * 4 + v];
            }
            Tbl[idx] = s;
            if (q < 4) m0 = fmaxf(m0, s);
            else if (q < 8) m1 = fmaxf(m1, s);
            else m2 = fmaxf(m2, s);
        }
#pragma unroll
        for (int o = 16; o > 0; o >>= 1) {
            m0 = fmaxf(m0, __shfl_xor_sync(0xffffffffu, m0, o));
            m1 = fmaxf(m1, __shfl_xor_sync(0xffffffffu, m1, o));
            m2 = fmaxf(m2, __shfl_xor_sync(0xffffffffu, m2, o));
        }
        if (lane == 0) { wacc[warp][0] = m0; wacc[warp][1] = m1; wacc[warp][2] = m2; }
        __syncthreads();
        if (tid == 0) {
            float a = wacc[0][0], b = wacc[0][1], c = wacc[0][2];
#pragma unroll
            for (int w = 1; w < 8; w++) {
                a = fmaxf(a, wacc[w][0]); b = fmaxf(b, wacc[w][1]); c = fmaxf(c, wacc[w][2]);
            }
            bmax_s = a + b + c;
        }
        __syncthreads();
    }
    const float bmax = bmax_s;

    const int base = tid * 16;
    const int wi = base >> 5;
    const int sh0 = base & 31;
    const unsigned x0 = Xs[wi], x1 = Xs[wi + 1];
    const unsigned y0 = Ys[wi], y1 = Ys[wi + 1];

    // ======== PASS 1: e -> shared, accumulate Ex[15] + Ey[15] (30 accs) ========
    {
        float acc[30];
#pragma unroll
        for (int j = 0; j < 30; j++) acc[j] = 0.f;

#pragma unroll 4
        for (int j = 0; j < 16; j++) {
            int sh = sh0 + j;
            unsigned bx = __funnelshift_r(x0, x1, sh);
            unsigned by = __funnelshift_r(y0, y1, sh);
            int u0 = (bx & 31) | ((by & 31) << 5);
            int u1 = ((bx >> 5) & 31) | (((by >> 5) & 31) << 5);
            int u2 = ((bx >> 10) & 31) | (((by >> 10) & 31) << 5);
            float s = Tbl[u0] + Tbl[1024 + u1] + Tbl[2048 + u2];
            float ev = __expf(s - bmax);
            ev = (base + j < LOUT) ? ev : 0.f;
            e_s[base + j] = ev;
#pragma unroll
            for (int i = 0; i < 15; i++) {
                acc[i]      += (bx & (1u << i)) ? ev : 0.f;
                acc[15 + i] += (by & (1u << i)) ? ev : 0.f;
            }
        }
#pragma unroll
        for (int j = 0; j < 30; j++) {
            float v = acc[j];
#pragma unroll
            for (int o = 16; o > 0; o >>= 1) v += __shfl_xor_sync(0xffffffffu, v, o);
            if (lane == 0) wacc[warp][j] = v;
        }
    }

    // ======== PASS 2: reload e, accumulate Exy[15] + E (16 accs) ========
    {
        float acc[15];
#pragma unroll
        for (int j = 0; j < 15; j++) acc[j] = 0.f;
        float accE = 0.f;

#pragma unroll 4
        for (int j = 0; j < 16; j++) {
            int sh = sh0 + j;
            unsigned bxy = __funnelshift_r(x0, x1, sh) & __funnelshift_r(y0, y1, sh);
            float ev = e_s[base + j];
            accE += ev;
#pragma unroll
            for (int i = 0; i < 15; i++)
                acc[i] += (bxy & (1u << i)) ? ev : 0.f;
        }
#pragma unroll
        for (int j = 0; j < 15; j++) {
            float v = acc[j];
#pragma unroll
            for (int o = 16; o > 0; o >>= 1) v += __shfl_xor_sync(0xffffffffu, v, o);
            if (lane == 0) wacc[warp][30 + j] = v;
        }
#pragma unroll
        for (int o = 16; o > 0; o >>= 1) accE += __shfl_xor_sync(0xffffffffu, accE, o);
        if (lane == 0) wacc[warp][45] = accE;
    }
    __syncthreads();

    if (tid < 46) {
        float s = 0.f;
#pragma unroll
        for (int w = 0; w < 8; w++) s += wacc[w][tid];
        fin[tid] = s;
    }
    __syncthreads();

    // ---- A[i][v] from (E, Ex, Ey, Exy) ----
    if (tid < NIV) {
        int i = tid >> 2, v = tid & 3;
        float E = fin[45], Ex = fin[i], Ey = fin[15 + i], Exy = fin[30 + i];
        A_s[tid] = (v == 3) ? Exy
                 : (v == 1) ? (Ex - Exy)
                 : (v == 2) ? (Ey - Exy)
                 : (E - Ex - Ey + Exy);
    }
    __syncthreads();

    // ---- out[c] = ob[c] + (WvWc*A)[c]/E ----
    if (tid < DC) {
        const float4* w4 = (const float4*)(g_WvWc + tid * NIV);
        float s = 0.f;
#pragma unroll
        for (int q = 0; q < NIV / 4; q++) {
            float4 f = w4[q];
            int j = q * 4;
            s += f.x * A_s[j] + f.y * A_s[j + 1] + f.z * A_s[j + 2] + f.w * A_s[j + 3];
        }
        out[(size_t)bid * DC + tid] = g_ob[tid] + s / fin[45];
    }
}

// ---------------- launch: ONE kernel ----------------
// Inputs: tokens, emb, conv_w, conv_b, Wq, bq, Wk, bk, Wv, bv  (bk drops out of softmax)
extern "C" void kernel_launch(void* const* d_in, const int* in_sizes, int n_in,
                              void* d_out, int out_size) {
    const int*   tokens = (const int*)  d_in[0];
    const float* emb    = (const float*)d_in[1];
    const float* conv_w = (const float*)d_in[2];
    const float* conv_b = (const float*)d_in[3];
    const float* Wq     = (const float*)d_in[4];
    const float* bq     = (const float*)d_in[5];
    const float* Wk     = (const float*)d_in[6];
    const float* Wv     = (const float*)d_in[8];
    const float* bv     = (const float*)d_in[9];
    float*       out    = (float*)d_out;

    seq_all<<<NBATCH, NTHR>>>(tokens, emb, conv_w, conv_b, Wq, bq, Wk, Wv, bv, out);
}